// round 5
// baseline (speedup 1.0000x reference)
#include <cuda_runtime.h>
#include <cuda_fp16.h>
#include <cstdint>

#define NN 10000
#define EE 160000
// log2(e)/sqrt(128) folded into Q so softmax runs in exp2 domain
#define QSCALE 0.12752532f

#define NSPLIT 15
#define CHUNK 672
#define NQT 79          // ceil(10000/128) Q tiles

// ------------- device scratch (static, zero-initialized, no allocation) -------------
__device__ float g_agg[NN * 128];        // stays zero between runs (conv re-zeros)
__device__ float g_h[NN * 128];
__device__ float g_ne[NN * 128];
__device__ __half g_Q[NN * 128];
__device__ __half g_K[NN * 128];
__device__ __half g_V[NN * 128];
__device__ float g_accum[128];           // stays zero between runs (final re-zeros)
__device__ float g_pm[NQT * NSPLIT * 128];
__device__ float g_pl[NQT * NSPLIT * 128];
__device__ float g_po[(size_t)NQT * NSPLIT * 128 * 128];

// ------------- helpers -------------
__device__ __forceinline__ uint32_t cvta_s(const void* p) {
    return (uint32_t)__cvta_generic_to_shared(p);
}
__device__ __forceinline__ void ldsm_x4(uint32_t& r0, uint32_t& r1, uint32_t& r2, uint32_t& r3, uint32_t a) {
    asm volatile("ldmatrix.sync.aligned.m8n8.x4.shared.b16 {%0,%1,%2,%3}, [%4];"
                 : "=r"(r0), "=r"(r1), "=r"(r2), "=r"(r3) : "r"(a));
}
__device__ __forceinline__ void ldsm_x4_t(uint32_t& r0, uint32_t& r1, uint32_t& r2, uint32_t& r3, uint32_t a) {
    asm volatile("ldmatrix.sync.aligned.m8n8.x4.trans.shared.b16 {%0,%1,%2,%3}, [%4];"
                 : "=r"(r0), "=r"(r1), "=r"(r2), "=r"(r3) : "r"(a));
}
__device__ __forceinline__ void mma_f16(float* c, const uint32_t* a, uint32_t b0, uint32_t b1) {
    asm volatile(
        "mma.sync.aligned.m16n8k16.row.col.f32.f16.f16.f32 "
        "{%0,%1,%2,%3},{%4,%5,%6,%7},{%8,%9},{%0,%1,%2,%3};\n"
        : "+f"(c[0]), "+f"(c[1]), "+f"(c[2]), "+f"(c[3])
        : "r"(a[0]), "r"(a[1]), "r"(a[2]), "r"(a[3]), "r"(b0), "r"(b1));
}
__device__ __forceinline__ void cp_async16(uint32_t s, const void* g) {
    asm volatile("cp.async.cg.shared.global [%0], [%1], 16;" :: "r"(s), "l"(g));
}
__device__ __forceinline__ void cp_commit() { asm volatile("cp.async.commit_group;"); }
template <int N> __device__ __forceinline__ void cp_wait() {
    asm volatile("cp.async.wait_group %0;" :: "n"(N));
}

// ------------- segment_sum(x[src], dst) -------------
__global__ void scatter_kernel(const float* __restrict__ xin, const int* __restrict__ ei, int useH) {
    const float* x = useH ? g_h : xin;
    long idx = (long)blockIdx.x * 256 + threadIdx.x;
    int e = (int)(idx >> 5);
    if (e >= EE) return;
    int q = ((int)idx & 31) * 4;
    int s = ei[e];
    int d = ei[EE + e];
    float4 v = *(const float4*)(x + (size_t)s * 128 + q);
    float* dp = g_agg + (size_t)d * 128 + q;
    asm volatile("red.global.add.v4.f32 [%0], {%1,%2,%3,%4};"
                 :: "l"(dp), "f"(v.x), "f"(v.y), "f"(v.z), "f"(v.w) : "memory");
}

// ------------- GraphConv: out = [relu](X@Wr + agg@Wl + b); zeros own agg rows after -------------
__global__ void __launch_bounds__(256) conv_kernel(const float* __restrict__ Xin,
                                                   const float* __restrict__ Wr,
                                                   const float* __restrict__ Wl,
                                                   const float* __restrict__ bias,
                                                   int stage) {
    __shared__ float As[64 * 36];
    __shared__ float Ws[32 * 128];
    const float* X = stage ? g_h : Xin;
    float* out = stage ? g_ne : g_h;
    int relu = stage ? 0 : 1;
    int tid = threadIdx.x;
    int rbase = blockIdx.x * 64;
    int cg = (tid & 7) * 16;
    int rg = tid >> 3;
    int r0 = rg * 2, r1 = r0 + 1;
    float acc0[16], acc1[16];
#pragma unroll
    for (int j = 0; j < 16; j++) { acc0[j] = 0.f; acc1[j] = 0.f; }

    for (int pass = 0; pass < 2; pass++) {
        const float* A = pass ? g_agg : X;
        const float* W = pass ? Wl : Wr;
        for (int ks = 0; ks < 4; ks++) {
            __syncthreads();
#pragma unroll
            for (int p = 0; p < 2; p++) {
                int slot = tid + p * 256;
                int ar = slot >> 3, ac = slot & 7;
                float4 v = make_float4(0.f, 0.f, 0.f, 0.f);
                int gr = rbase + ar;
                if (gr < NN) v = *(const float4*)(A + (size_t)gr * 128 + ks * 32 + ac * 4);
                *(float4*)(As + ar * 36 + ac * 4) = v;
            }
#pragma unroll
            for (int p = 0; p < 4; p++) {
                int slot = tid + p * 256;
                int wr = slot >> 5, wc = slot & 31;
                *(float4*)(Ws + wr * 128 + wc * 4) =
                    *(const float4*)(W + (size_t)(ks * 32 + wr) * 128 + wc * 4);
            }
            __syncthreads();
#pragma unroll
            for (int kk = 0; kk < 32; kk++) {
                float a0 = As[r0 * 36 + kk], a1 = As[r1 * 36 + kk];
#pragma unroll
                for (int j = 0; j < 16; j++) {
                    float wv = Ws[kk * 128 + cg + j];
                    acc0[j] += a0 * wv;
                    acc1[j] += a1 * wv;
                }
            }
        }
    }

    // re-zero own agg rows (keeps replay invariant: g_agg zero before next scatter)
    {
        float4 z = make_float4(0.f, 0.f, 0.f, 0.f);
#pragma unroll
        for (int p = 0; p < 8; p++) {
            int slot = tid + p * 256;
            int r = slot >> 5, c = slot & 31;
            int gr = rbase + r;
            if (gr < NN) *(float4*)(g_agg + (size_t)gr * 128 + c * 4) = z;
        }
    }

    int gr0 = rbase + r0, gr1 = rbase + r1;
    float4 o0[4], o1[4];
#pragma unroll
    for (int q = 0; q < 4; q++) {
        float b0 = bias[cg + 4 * q + 0], b1 = bias[cg + 4 * q + 1];
        float b2 = bias[cg + 4 * q + 2], b3 = bias[cg + 4 * q + 3];
        o0[q] = make_float4(acc0[4 * q] + b0, acc0[4 * q + 1] + b1, acc0[4 * q + 2] + b2, acc0[4 * q + 3] + b3);
        o1[q] = make_float4(acc1[4 * q] + b0, acc1[4 * q + 1] + b1, acc1[4 * q + 2] + b2, acc1[4 * q + 3] + b3);
        if (relu) {
            o0[q].x = fmaxf(o0[q].x, 0.f); o0[q].y = fmaxf(o0[q].y, 0.f);
            o0[q].z = fmaxf(o0[q].z, 0.f); o0[q].w = fmaxf(o0[q].w, 0.f);
            o1[q].x = fmaxf(o1[q].x, 0.f); o1[q].y = fmaxf(o1[q].y, 0.f);
            o1[q].z = fmaxf(o1[q].z, 0.f); o1[q].w = fmaxf(o1[q].w, 0.f);
        }
    }
#pragma unroll
    for (int q = 0; q < 4; q++) {
        if (gr0 < NN) *(float4*)(out + (size_t)gr0 * 128 + cg + 4 * q) = o0[q];
        if (gr1 < NN) *(float4*)(out + (size_t)gr1 * 128 + cg + 4 * q) = o1[q];
    }
}

// ------------- QKV with fused (b + global@Wg + bg): out_h = (ne@W + cbias)*scale -> fp16 -------------
__global__ void __launch_bounds__(256) qkv_kernel(const float* __restrict__ gi,
                                                  const float* __restrict__ WQ, const float* __restrict__ bQ,
                                                  const float* __restrict__ WQg, const float* __restrict__ bQg,
                                                  const float* __restrict__ WK, const float* __restrict__ bK,
                                                  const float* __restrict__ WKg, const float* __restrict__ bKg,
                                                  const float* __restrict__ WV, const float* __restrict__ bV,
                                                  const float* __restrict__ WVg, const float* __restrict__ bVg) {
    __shared__ float As[64 * 36];
    __shared__ float Ws[32 * 128];
    __shared__ float cb_s[128];
    int m = blockIdx.y;
    const float* W = m == 0 ? WQ : (m == 1 ? WK : WV);
    __half* out = m == 0 ? g_Q : (m == 1 ? g_K : g_V);
    float scale = m == 0 ? QSCALE : 1.0f;
    int tid = threadIdx.x;
    if (tid < 128) {
        const float* b = m == 0 ? bQ : (m == 1 ? bK : bV);
        const float* bg = m == 0 ? bQg : (m == 1 ? bKg : bVg);
        const float* Wg = m == 0 ? WQg : (m == 1 ? WKg : WVg);
        float s = b[tid] + bg[tid];
        for (int i = 0; i < 64; i++) s += gi[i] * Wg[i * 128 + tid];
        cb_s[tid] = s;
    }
    int rbase = blockIdx.x * 64;
    int cg = (tid & 7) * 16;
    int rg = tid >> 3;
    int r0 = rg * 2, r1 = r0 + 1;
    float acc0[16], acc1[16];
#pragma unroll
    for (int j = 0; j < 16; j++) { acc0[j] = 0.f; acc1[j] = 0.f; }

    for (int ks = 0; ks < 4; ks++) {
        __syncthreads();
#pragma unroll
        for (int p = 0; p < 2; p++) {
            int slot = tid + p * 256;
            int ar = slot >> 3, ac = slot & 7;
            float4 v = make_float4(0.f, 0.f, 0.f, 0.f);
            int gr = rbase + ar;
            if (gr < NN) v = *(const float4*)(g_ne + (size_t)gr * 128 + ks * 32 + ac * 4);
            *(float4*)(As + ar * 36 + ac * 4) = v;
        }
#pragma unroll
        for (int p = 0; p < 4; p++) {
            int slot = tid + p * 256;
            int wr = slot >> 5, wc = slot & 31;
            *(float4*)(Ws + wr * 128 + wc * 4) =
                *(const float4*)(W + (size_t)(ks * 32 + wr) * 128 + wc * 4);
        }
        __syncthreads();
#pragma unroll
        for (int kk = 0; kk < 32; kk++) {
            float a0 = As[r0 * 36 + kk], a1 = As[r1 * 36 + kk];
#pragma unroll
            for (int j = 0; j < 16; j++) {
                float wv = Ws[kk * 128 + cg + j];
                acc0[j] += a0 * wv;
                acc1[j] += a1 * wv;
            }
        }
    }
    int gr0 = rbase + r0, gr1 = rbase + r1;
    __half h0[16], h1[16];
#pragma unroll
    for (int j = 0; j < 16; j++) {
        float cb = cb_s[cg + j];
        h0[j] = __float2half_rn((acc0[j] + cb) * scale);
        h1[j] = __float2half_rn((acc1[j] + cb) * scale);
    }
    if (gr0 < NN) {
        *(uint4*)(out + (size_t)gr0 * 128 + cg) = *(uint4*)h0;
        *(uint4*)(out + (size_t)gr0 * 128 + cg + 8) = *(uint4*)(h0 + 8);
    }
    if (gr1 < NN) {
        *(uint4*)(out + (size_t)gr1 * 128 + cg) = *(uint4*)h1;
        *(uint4*)(out + (size_t)gr1 * 128 + cg + 8) = *(uint4*)(h1 + 8);
    }
}

// ------------- split-KV flash attention (Br=128, Bc=64, 2 CTAs/SM) -------------
#define KSTR 272
#define SM_ST (128 * KSTR)          // Q region size
#define STAGE_BYTES (128 * KSTR)    // 64 K rows + 64 V rows
#define SMEM_TOTAL (SM_ST + 2 * STAGE_BYTES)   // 104448

__global__ void __launch_bounds__(256, 2) attn_kernel() {
    extern __shared__ char sm[];
    __half* Qs = (__half*)sm;
    int tid = threadIdx.x, lane = tid & 31, w = tid >> 5;
    int unit = blockIdx.x;
    int qtile = unit / NSPLIT, split = unit - qtile * NSPLIT;
    int rbase = qtile * 128;
    int kv0 = split * CHUNK;
    int kv1 = min(kv0 + CHUNK, NN);
    int niter = (kv1 - kv0 + 63) >> 6;

    // load Q tile (OOB rows clamped; excluded at merge)
    for (int i = tid; i < 128 * 16; i += 256) {
        int r = i >> 4, ch = i & 15;
        int gr = min(rbase + r, NN - 1);
        *(uint4*)((char*)Qs + r * KSTR + ch * 16) =
            *(const uint4*)((const char*)g_Q + (size_t)gr * 256 + ch * 16);
    }

    // issue stage 0 K/V loads (64 rows K + 64 rows V)
    {
        char* stg = sm + SM_ST;
#pragma unroll
        for (int p = 0; p < 8; p++) {
            int i = p * 256 + tid;
            int sel = i >= 1024;
            int ii = i & 1023;
            int r = ii >> 4, ch = ii & 15;
            int gr = min(kv0 + r, NN - 1);
            const char* src = sel ? (const char*)g_V : (const char*)g_K;
            uint32_t dst = cvta_s(stg + (sel ? 64 * KSTR : 0) + r * KSTR + ch * 16);
            cp_async16(dst, src + (size_t)gr * 256 + ch * 16);
        }
        cp_commit();
    }
    __syncthreads();

    float M0 = -1e30f, M1 = -1e30f, l0 = 0.f, l1 = 0.f;
    float o[64];
#pragma unroll
    for (int i = 0; i < 64; i++) o[i] = 0.f;

    int g = lane >> 3, idx = lane & 7;

    for (int it = 0; it < niter; it++) {
        int jb = kv0 + it * 64;
        char* stg = sm + SM_ST + (it & 1) * STAGE_BYTES;
        __half* Ks = (__half*)stg;
        __half* Vs = (__half*)(stg + 64 * KSTR);

        // prefetch next stage
        if (it + 1 < niter) {
            int jn = jb + 64;
            char* nstg = sm + SM_ST + ((it + 1) & 1) * STAGE_BYTES;
#pragma unroll
            for (int p = 0; p < 8; p++) {
                int i = p * 256 + tid;
                int sel = i >= 1024;
                int ii = i & 1023;
                int r = ii >> 4, ch = ii & 15;
                int gr = min(jn + r, NN - 1);
                const char* src = sel ? (const char*)g_V : (const char*)g_K;
                uint32_t dst = cvta_s(nstg + (sel ? 64 * KSTR : 0) + r * KSTR + ch * 16);
                cp_async16(dst, src + (size_t)gr * 256 + ch * 16);
            }
            cp_commit();
            cp_wait<1>();
        } else {
            cp_wait<0>();
        }
        __syncthreads();

        float s[32];
#pragma unroll
        for (int i = 0; i < 32; i++) s[i] = 0.f;

        // S = Q @ K^T   (Q frags re-loaded per k-tile to cap registers)
#pragma unroll
        for (int kt = 0; kt < 8; kt++) {
            uint32_t qa[4];
            int qrow = w * 16 + (g & 1) * 8 + idx;
            ldsm_x4(qa[0], qa[1], qa[2], qa[3],
                    cvta_s((char*)Qs + qrow * KSTR + kt * 32 + (g >> 1) * 16));
#pragma unroll
            for (int nt2 = 0; nt2 < 4; nt2++) {
                int row = nt2 * 16 + (g & 2) * 4 + idx;
                uint32_t b0, b1, b2, b3;
                ldsm_x4(b0, b1, b2, b3,
                        cvta_s((char*)Ks + row * KSTR + kt * 32 + (g & 1) * 16));
                mma_f16(s + (2 * nt2) * 4, qa, b0, b1);
                mma_f16(s + (2 * nt2 + 1) * 4, qa, b2, b3);
            }
        }

        // mask tail keys
        if (jb + 64 > kv1) {
#pragma unroll
            for (int nt = 0; nt < 8; nt++) {
                int j0 = jb + nt * 8 + 2 * (lane & 3);
                if (j0 >= kv1) { s[nt * 4 + 0] = -1e30f; s[nt * 4 + 2] = -1e30f; }
                if (j0 + 1 >= kv1) { s[nt * 4 + 1] = -1e30f; s[nt * 4 + 3] = -1e30f; }
            }
        }

        // online softmax (exp2 domain, half2 P via ex2.approx.f16x2)
        float m0 = -1e30f, m1 = -1e30f;
#pragma unroll
        for (int nt = 0; nt < 8; nt++) {
            m0 = fmaxf(m0, fmaxf(s[nt * 4 + 0], s[nt * 4 + 1]));
            m1 = fmaxf(m1, fmaxf(s[nt * 4 + 2], s[nt * 4 + 3]));
        }
        m0 = fmaxf(m0, __shfl_xor_sync(0xffffffffu, m0, 1));
        m0 = fmaxf(m0, __shfl_xor_sync(0xffffffffu, m0, 2));
        m1 = fmaxf(m1, __shfl_xor_sync(0xffffffffu, m1, 1));
        m1 = fmaxf(m1, __shfl_xor_sync(0xffffffffu, m1, 2));
        float Mn0 = fmaxf(M0, m0), Mn1 = fmaxf(M1, m1);
        float sc0 = exp2f(M0 - Mn0), sc1 = exp2f(M1 - Mn1);
        M0 = Mn0; M1 = Mn1;

        uint32_t pr[16];
        float r0 = 0.f, r1 = 0.f;
#pragma unroll
        for (int nt = 0; nt < 8; nt++) {
            __half2 ha = h2exp2(__floats2half2_rn(s[nt * 4 + 0] - M0, s[nt * 4 + 1] - M0));
            __half2 hb = h2exp2(__floats2half2_rn(s[nt * 4 + 2] - M1, s[nt * 4 + 3] - M1));
            pr[nt * 2 + 0] = *reinterpret_cast<uint32_t*>(&ha);
            pr[nt * 2 + 1] = *reinterpret_cast<uint32_t*>(&hb);
            float2 fa = __half22float2(ha), fb = __half22float2(hb);
            r0 += fa.x + fa.y;
            r1 += fb.x + fb.y;
        }
        r0 += __shfl_xor_sync(0xffffffffu, r0, 1);
        r0 += __shfl_xor_sync(0xffffffffu, r0, 2);
        r1 += __shfl_xor_sync(0xffffffffu, r1, 1);
        r1 += __shfl_xor_sync(0xffffffffu, r1, 2);
        l0 = l0 * sc0 + r0;
        l1 = l1 * sc1 + r1;
        if (!__all_sync(0xffffffffu, (sc0 == 1.f) && (sc1 == 1.f))) {
#pragma unroll
            for (int nt = 0; nt < 16; nt++) {
                o[nt * 4 + 0] *= sc0; o[nt * 4 + 1] *= sc0;
                o[nt * 4 + 2] *= sc1; o[nt * 4 + 3] *= sc1;
            }
        }

        // O += P @ V
#pragma unroll
        for (int kt = 0; kt < 4; kt++) {
#pragma unroll
            for (int nt2 = 0; nt2 < 8; nt2++) {
                int row = kt * 16 + (g & 1) * 8 + idx;
                uint32_t b0, b1, b2, b3;
                ldsm_x4_t(b0, b1, b2, b3,
                          cvta_s((char*)Vs + row * KSTR + nt2 * 32 + (g >> 1) * 16));
                mma_f16(o + (2 * nt2) * 4, pr + 4 * kt, b0, b1);
                mma_f16(o + (2 * nt2 + 1) * 4, pr + 4 * kt, b2, b3);
            }
        }
        __syncthreads();
    }

    // write partials (unnormalized o, plus m, l)
    int rr0 = w * 16 + (lane >> 2);
    int rr1 = rr0 + 8;
    size_t ubase = (size_t)unit * 128;
    if ((lane & 3) == 0) {
        g_pm[ubase + rr0] = M0;
        g_pl[ubase + rr0] = l0;
        g_pm[ubase + rr1] = M1;
        g_pl[ubase + rr1] = l1;
    }
#pragma unroll
    for (int nt = 0; nt < 16; nt++) {
        int c = nt * 8 + 2 * (lane & 3);
        *(float2*)&g_po[(ubase + rr0) * 128 + c] = make_float2(o[nt * 4 + 0], o[nt * 4 + 1]);
        *(float2*)&g_po[(ubase + rr1) * 128 + c] = make_float2(o[nt * 4 + 2], o[nt * 4 + 3]);
    }
}

// ------------- merge splits + column mean-sum -------------
__global__ void __launch_bounds__(128) merge_kernel() {
    int c = threadIdx.x;
    int rstart = blockIdx.x * 16;
    float acc = 0.f;
    for (int i = 0; i < 16; i++) {
        int r = rstart + i;
        if (r >= NN) break;
        int tile = r >> 7, row = r & 127;
        int base = tile * (NSPLIT * 128) + row;
        float M = -1e30f;
#pragma unroll
        for (int s = 0; s < NSPLIT; s++) M = fmaxf(M, g_pm[base + s * 128]);
        float L = 0.f, oc = 0.f;
#pragma unroll
        for (int s = 0; s < NSPLIT; s++) {
            float sc = exp2f(g_pm[base + s * 128] - M);
            L += g_pl[base + s * 128] * sc;
            oc += g_po[(size_t)(base + s * 128) * 128 + c] * sc;
        }
        acc += oc / L;
    }
    atomicAdd(&g_accum[c], acc);
}

// ------------- mean -> Wo -> MLP -> softmax; re-zeros g_accum -------------
__global__ void __launch_bounds__(128) final_kernel(const float* Wo, const float* bo,
                                                    const float* W1, const float* b1v,
                                                    const float* W2, const float* b2v,
                                                    const float* W3, const float* b3v,
                                                    float* out) {
    __shared__ float v0[128], v1[128], v2[64], v3[32], red[2];
    int t = threadIdx.x;
    v0[t] = g_accum[t] * (1.0f / NN);
    g_accum[t] = 0.f;   // replay invariant
    __syncthreads();
    float s = bo[t];
    for (int i = 0; i < 128; i++) s += v0[i] * Wo[i * 128 + t];
    v1[t] = s;
    __syncthreads();
    if (t < 64) {
        float s2 = b1v[t];
        for (int i = 0; i < 128; i++) s2 += v1[i] * W1[i * 64 + t];
        v2[t] = fmaxf(s2, 0.f);
    }
    __syncthreads();
    if (t < 32) {
        float s3 = b2v[t];
        for (int i = 0; i < 64; i++) s3 += v2[i] * W2[i * 32 + t];
        v3[t] = fmaxf(s3, 0.f);
    }
    __syncthreads();
    float lg = b3v[t];
    for (int i = 0; i < 32; i++) lg += v3[i] * W3[i * 128 + t];
    v1[t] = lg;
    __syncthreads();
    if (t == 0) {
        float mx = -1e30f;
        for (int i = 0; i < 128; i++) mx = fmaxf(mx, v1[i]);
        float sm = 0.f;
        for (int i = 0; i < 128; i++) sm += expf(v1[i] - mx);
        red[0] = mx; red[1] = sm;
    }
    __syncthreads();
    out[t] = expf(lg - red[0]) / red[1];
}

// ------------- launch -------------
extern "C" void kernel_launch(void* const* d_in, const int* in_sizes, int n_in,
                              void* d_out, int out_size) {
    const float* nf = (const float*)d_in[0];
    const float* gi = (const float*)d_in[1];
    const int* ei = (const int*)d_in[2];
    const float* W1_root = (const float*)d_in[3];
    const float* W1_rel = (const float*)d_in[4];
    const float* b1 = (const float*)d_in[5];
    const float* W2_root = (const float*)d_in[6];
    const float* W2_rel = (const float*)d_in[7];
    const float* b2 = (const float*)d_in[8];
    const float* WQ = (const float*)d_in[9];
    const float* bQ = (const float*)d_in[10];
    const float* WK = (const float*)d_in[11];
    const float* bK = (const float*)d_in[12];
    const float* WV = (const float*)d_in[13];
    const float* bV = (const float*)d_in[14];
    const float* WQg = (const float*)d_in[15];
    const float* bQg = (const float*)d_in[16];
    const float* WKg = (const float*)d_in[17];
    const float* bKg = (const float*)d_in[18];
    const float* WVg = (const float*)d_in[19];
    const float* bVg = (const float*)d_in[20];
    const float* Wo = (const float*)d_in[21];
    const float* bo = (const float*)d_in[22];
    const float* Wfc1 = (const float*)d_in[23];
    const float* bfc1 = (const float*)d_in[24];
    const float* Wfc2 = (const float*)d_in[25];
    const float* bfc2 = (const float*)d_in[26];
    const float* Wfc3 = (const float*)d_in[27];
    const float* bfc3 = (const float*)d_in[28];

    static int attr_set = 0;
    if (!attr_set) {
        cudaFuncSetAttribute(attn_kernel, cudaFuncAttributeMaxDynamicSharedMemorySize, SMEM_TOTAL);
        attr_set = 1;
    }

    scatter_kernel<<<20000, 256>>>(nf, ei, 0);                                   // 0
    conv_kernel<<<157, 256>>>(nf, W1_root, W1_rel, b1, 0);                       // 1
    scatter_kernel<<<20000, 256>>>(nf, ei, 1);                                   // 2
    conv_kernel<<<157, 256>>>(nf, W2_root, W2_rel, b2, 1);                       // 3
    qkv_kernel<<<dim3(157, 3), 256>>>(gi, WQ, bQ, WQg, bQg,
                                      WK, bK, WKg, bKg, WV, bV, WVg, bVg);       // 4
    attn_kernel<<<NQT * NSPLIT, 256, SMEM_TOTAL>>>();                            // 5 <- ncu -s 5 captures this
    merge_kernel<<<625, 128>>>();                                                // 6
    final_kernel<<<1, 128>>>(Wo, bo, Wfc1, bfc1, Wfc2, bfc2, Wfc3, bfc3, (float*)d_out);  // 7
}

// round 8
// speedup vs baseline: 1.5905x; 1.5905x over previous
#include <cuda_runtime.h>
#include <cuda_fp16.h>
#include <cstdint>

#define NN 10000
#define EE 160000
// log2(e)/sqrt(128) folded into Q so softmax runs in exp2 domain
#define QSCALE 0.12752532f

#define NSPLIT 8
#define CHUNK 1280
#define NQT 79          // ceil(10000/128) Q tiles

// ------------- device scratch (static, zero-initialized, no allocation) -------------
__device__ float g_aggA[NN * 128];       // scatter#1 target; zeroed by conv stage 1
__device__ float g_aggB[NN * 128];       // scatter#2 target; zeroed by qkv (m==0)
__device__ float g_h[NN * 128];
__device__ float g_ne[NN * 128];
__device__ __half g_Q[NN * 128];
__device__ __half g_K[NN * 128];
__device__ __half g_V[NN * 128];
__device__ float g_accum[128];           // zeroed by final_kernel after read
__device__ float g_pm[NQT * NSPLIT * 128];
__device__ float g_pl[NQT * NSPLIT * 128];
__device__ float g_po[(size_t)NQT * NSPLIT * 128 * 128];

// ------------- helpers -------------
__device__ __forceinline__ uint32_t cvta_s(const void* p) {
    return (uint32_t)__cvta_generic_to_shared(p);
}
__device__ __forceinline__ void ldsm_x4(uint32_t& r0, uint32_t& r1, uint32_t& r2, uint32_t& r3, uint32_t a) {
    asm volatile("ldmatrix.sync.aligned.m8n8.x4.shared.b16 {%0,%1,%2,%3}, [%4];"
                 : "=r"(r0), "=r"(r1), "=r"(r2), "=r"(r3) : "r"(a));
}
__device__ __forceinline__ void ldsm_x4_t(uint32_t& r0, uint32_t& r1, uint32_t& r2, uint32_t& r3, uint32_t a) {
    asm volatile("ldmatrix.sync.aligned.m8n8.x4.trans.shared.b16 {%0,%1,%2,%3}, [%4];"
                 : "=r"(r0), "=r"(r1), "=r"(r2), "=r"(r3) : "r"(a));
}
__device__ __forceinline__ void mma_f16(float* c, const uint32_t* a, uint32_t b0, uint32_t b1) {
    asm volatile(
        "mma.sync.aligned.m16n8k16.row.col.f32.f16.f16.f32 "
        "{%0,%1,%2,%3},{%4,%5,%6,%7},{%8,%9},{%0,%1,%2,%3};\n"
        : "+f"(c[0]), "+f"(c[1]), "+f"(c[2]), "+f"(c[3])
        : "r"(a[0]), "r"(a[1]), "r"(a[2]), "r"(a[3]), "r"(b0), "r"(b1));
}
__device__ __forceinline__ uint32_t packh2(float lo, float hi) {
    __half2 h = __floats2half2_rn(lo, hi);
    return *reinterpret_cast<uint32_t*>(&h);
}
__device__ __forceinline__ void cp_async16(uint32_t s, const void* g) {
    asm volatile("cp.async.cg.shared.global [%0], [%1], 16;" :: "r"(s), "l"(g));
}
__device__ __forceinline__ void cp_commit() { asm volatile("cp.async.commit_group;"); }
template <int N> __device__ __forceinline__ void cp_wait() {
    asm volatile("cp.async.wait_group %0;" :: "n"(N));
}

// ------------- segment_sum(x[src], dst) -------------
__global__ void scatter_kernel(const float* __restrict__ xin, const int* __restrict__ ei, int useH) {
    const float* x = useH ? g_h : xin;
    float* agg = useH ? g_aggB : g_aggA;
    long idx = (long)blockIdx.x * 256 + threadIdx.x;
    int e = (int)(idx >> 5);
    if (e >= EE) return;
    int q = ((int)idx & 31) * 4;
    int s = ei[e];
    int d = ei[EE + e];
    float4 v = *(const float4*)(x + (size_t)s * 128 + q);
    float* dp = agg + (size_t)d * 128 + q;
    asm volatile("red.global.add.v4.f32 [%0], {%1,%2,%3,%4};"
                 :: "l"(dp), "f"(v.x), "f"(v.y), "f"(v.z), "f"(v.w) : "memory");
}

// ------------- GraphConv: out = [relu](X@Wr + agg@Wl + b) -------------
// grid (157, 2): 64 rows x 64 cols per CTA. Stage 1 additionally zeros its
// g_aggA tile (safe: nothing reads A after stage 0; kernel boundary syncs).
__global__ void __launch_bounds__(256) conv_kernel(const float* __restrict__ Xin,
                                                   const float* __restrict__ Wr,
                                                   const float* __restrict__ Wl,
                                                   const float* __restrict__ bias,
                                                   int stage) {
    __shared__ float As[64 * 36];
    __shared__ float Ws[32 * 64];
    const float* X = stage ? g_h : Xin;
    const float* AGG = stage ? g_aggB : g_aggA;
    float* out = stage ? g_ne : g_h;
    int relu = stage ? 0 : 1;
    int tid = threadIdx.x;
    int rbase = blockIdx.x * 64;
    int cbase = blockIdx.y * 64;
    int cg = (tid & 7) * 8;
    int rg = tid >> 3;
    int r0 = rg * 2, r1 = r0 + 1;
    float acc0[8], acc1[8];
#pragma unroll
    for (int j = 0; j < 8; j++) { acc0[j] = 0.f; acc1[j] = 0.f; }

    for (int pass = 0; pass < 2; pass++) {
        const float* A = pass ? AGG : X;
        const float* W = pass ? Wl : Wr;
        for (int ks = 0; ks < 4; ks++) {
            __syncthreads();
#pragma unroll
            for (int p = 0; p < 2; p++) {           // As: 64 rows x 32 cols
                int slot = tid + p * 256;
                int ar = slot >> 3, ac = slot & 7;
                float4 v = make_float4(0.f, 0.f, 0.f, 0.f);
                int gr = rbase + ar;
                if (gr < NN) v = *(const float4*)(A + (size_t)gr * 128 + ks * 32 + ac * 4);
                *(float4*)(As + ar * 36 + ac * 4) = v;
            }
#pragma unroll
            for (int p = 0; p < 2; p++) {           // Ws: 32 k-rows x 64 cols
                int slot = tid + p * 256;
                int wr = slot >> 4, wc = slot & 15;
                *(float4*)(Ws + wr * 64 + wc * 4) =
                    *(const float4*)(W + (size_t)(ks * 32 + wr) * 128 + cbase + wc * 4);
            }
            __syncthreads();
#pragma unroll
            for (int kk = 0; kk < 32; kk++) {
                float a0 = As[r0 * 36 + kk], a1 = As[r1 * 36 + kk];
#pragma unroll
                for (int j = 0; j < 8; j++) {
                    float wv = Ws[kk * 64 + cg + j];
                    acc0[j] += a0 * wv;
                    acc1[j] += a1 * wv;
                }
            }
        }
    }

    // stage 1: zero our tile of g_aggA (A fully consumed by stage 0; replay invariant)
    if (stage) {
        float4 z = make_float4(0.f, 0.f, 0.f, 0.f);
#pragma unroll
        for (int p = 0; p < 4; p++) {
            int slot = tid + p * 256;
            int r = slot >> 4, c = slot & 15;
            int gr = rbase + r;
            if (gr < NN) *(float4*)(g_aggA + (size_t)gr * 128 + cbase + c * 4) = z;
        }
    }

    int gr0 = rbase + r0, gr1 = rbase + r1;
    float4 o0[2], o1[2];
#pragma unroll
    for (int q = 0; q < 2; q++) {
        float b0 = bias[cbase + cg + 4 * q + 0], b1 = bias[cbase + cg + 4 * q + 1];
        float b2 = bias[cbase + cg + 4 * q + 2], b3 = bias[cbase + cg + 4 * q + 3];
        o0[q] = make_float4(acc0[4 * q] + b0, acc0[4 * q + 1] + b1, acc0[4 * q + 2] + b2, acc0[4 * q + 3] + b3);
        o1[q] = make_float4(acc1[4 * q] + b0, acc1[4 * q + 1] + b1, acc1[4 * q + 2] + b2, acc1[4 * q + 3] + b3);
        if (relu) {
            o0[q].x = fmaxf(o0[q].x, 0.f); o0[q].y = fmaxf(o0[q].y, 0.f);
            o0[q].z = fmaxf(o0[q].z, 0.f); o0[q].w = fmaxf(o0[q].w, 0.f);
            o1[q].x = fmaxf(o1[q].x, 0.f); o1[q].y = fmaxf(o1[q].y, 0.f);
            o1[q].z = fmaxf(o1[q].z, 0.f); o1[q].w = fmaxf(o1[q].w, 0.f);
        }
    }
#pragma unroll
    for (int q = 0; q < 2; q++) {
        if (gr0 < NN) *(float4*)(out + (size_t)gr0 * 128 + cbase + cg + 4 * q) = o0[q];
        if (gr1 < NN) *(float4*)(out + (size_t)gr1 * 128 + cbase + cg + 4 * q) = o1[q];
    }
}

// ------------- QKV with fused (b + global@Wg + bg): grid (157,2,3), 64x64 tiles -------------
// m==0 CTAs also zero their g_aggB tile (B fully consumed by conv stage 1).
__global__ void __launch_bounds__(256) qkv_kernel(const float* __restrict__ gi,
                                                  const float* __restrict__ WQ, const float* __restrict__ bQ,
                                                  const float* __restrict__ WQg, const float* __restrict__ bQg,
                                                  const float* __restrict__ WK, const float* __restrict__ bK,
                                                  const float* __restrict__ WKg, const float* __restrict__ bKg,
                                                  const float* __restrict__ WV, const float* __restrict__ bV,
                                                  const float* __restrict__ WVg, const float* __restrict__ bVg) {
    __shared__ float As[64 * 36];
    __shared__ float Ws[32 * 64];
    __shared__ float cb_s[64];
    int m = blockIdx.z;
    const float* W = m == 0 ? WQ : (m == 1 ? WK : WV);
    __half* out = m == 0 ? g_Q : (m == 1 ? g_K : g_V);
    float scale = m == 0 ? QSCALE : 1.0f;
    int tid = threadIdx.x;
    int rbase = blockIdx.x * 64;
    int cbase = blockIdx.y * 64;
    if (tid < 64) {
        const float* b = m == 0 ? bQ : (m == 1 ? bK : bV);
        const float* bg = m == 0 ? bQg : (m == 1 ? bKg : bVg);
        const float* Wg = m == 0 ? WQg : (m == 1 ? WKg : WVg);
        int c = cbase + tid;
        float s = b[c] + bg[c];
        for (int i = 0; i < 64; i++) s += gi[i] * Wg[i * 128 + c];
        cb_s[tid] = s;
    }
    int cg = (tid & 7) * 8;
    int rg = tid >> 3;
    int r0 = rg * 2, r1 = r0 + 1;
    float acc0[8], acc1[8];
#pragma unroll
    for (int j = 0; j < 8; j++) { acc0[j] = 0.f; acc1[j] = 0.f; }

    for (int ks = 0; ks < 4; ks++) {
        __syncthreads();
#pragma unroll
        for (int p = 0; p < 2; p++) {
            int slot = tid + p * 256;
            int ar = slot >> 3, ac = slot & 7;
            float4 v = make_float4(0.f, 0.f, 0.f, 0.f);
            int gr = rbase + ar;
            if (gr < NN) v = *(const float4*)(g_ne + (size_t)gr * 128 + ks * 32 + ac * 4);
            *(float4*)(As + ar * 36 + ac * 4) = v;
        }
#pragma unroll
        for (int p = 0; p < 2; p++) {
            int slot = tid + p * 256;
            int wr = slot >> 4, wc = slot & 15;
            *(float4*)(Ws + wr * 64 + wc * 4) =
                *(const float4*)(W + (size_t)(ks * 32 + wr) * 128 + cbase + wc * 4);
        }
        __syncthreads();
#pragma unroll
        for (int kk = 0; kk < 32; kk++) {
            float a0 = As[r0 * 36 + kk], a1 = As[r1 * 36 + kk];
#pragma unroll
            for (int j = 0; j < 8; j++) {
                float wv = Ws[kk * 64 + cg + j];
                acc0[j] += a0 * wv;
                acc1[j] += a1 * wv;
            }
        }
    }

    // m==0: zero our tile of g_aggB (replay invariant; race-free after conv stage 1)
    if (m == 0) {
        float4 z = make_float4(0.f, 0.f, 0.f, 0.f);
#pragma unroll
        for (int p = 0; p < 4; p++) {
            int slot = tid + p * 256;
            int r = slot >> 4, c = slot & 15;
            int gr = rbase + r;
            if (gr < NN) *(float4*)(g_aggB + (size_t)gr * 128 + cbase + c * 4) = z;
        }
    }

    int gr0 = rbase + r0, gr1 = rbase + r1;
    __half h0[8], h1[8];
#pragma unroll
    for (int j = 0; j < 8; j++) {
        float cb = cb_s[cg + j];
        h0[j] = __float2half_rn((acc0[j] + cb) * scale);
        h1[j] = __float2half_rn((acc1[j] + cb) * scale);
    }
    if (gr0 < NN) *(uint4*)(out + (size_t)gr0 * 128 + cbase + cg) = *(uint4*)h0;
    if (gr1 < NN) *(uint4*)(out + (size_t)gr1 * 128 + cbase + cg) = *(uint4*)h1;
}

// ------------- split-KV flash attention (proven 719µs version: Br=128, Bc=128) -------------
#define KSTR 272
#define SM_Q 0
#define SM_ST (128 * KSTR)
#define STAGE_BYTES (2 * 128 * KSTR)
#define SMEM_TOTAL (128 * KSTR + 2 * STAGE_BYTES)

__global__ void __launch_bounds__(256, 1) attn_kernel() {
    extern __shared__ char sm[];
    __half* Qs = (__half*)(sm + SM_Q);
    int tid = threadIdx.x, lane = tid & 31, w = tid >> 5;
    int unit = blockIdx.x;
    int qtile = unit / NSPLIT, split = unit - qtile * NSPLIT;
    int rbase = qtile * 128;
    int kv0 = split * CHUNK;
    int kv1 = min(kv0 + CHUNK, NN);
    int niter = (kv1 - kv0 + 127) >> 7;

    // load Q tile (OOB rows clamped; excluded at merge)
    for (int i = tid; i < 128 * 16; i += 256) {
        int r = i >> 4, ch = i & 15;
        int gr = min(rbase + r, NN - 1);
        *(uint4*)((char*)Qs + r * KSTR + ch * 16) =
            *(const uint4*)((const char*)g_Q + (size_t)gr * 256 + ch * 16);
    }

    // issue stage 0 K/V loads
    {
        int jb = kv0;
#pragma unroll
        for (int p = 0; p < 16; p++) {
            int i = p * 256 + tid;
            int sel = i >= 2048;
            int ii = i & 2047;
            int r = ii >> 4, ch = ii & 15;
            int gr = min(jb + r, NN - 1);
            const char* src = sel ? (const char*)g_V : (const char*)g_K;
            uint32_t dst = cvta_s(sm + SM_ST + (sel ? 128 * KSTR : 0) + r * KSTR + ch * 16);
            cp_async16(dst, src + (size_t)gr * 256 + ch * 16);
        }
        cp_commit();
    }
    __syncthreads();

    // preload Q a-frags
    uint32_t qa[8][4];
    {
        int g = lane >> 3, idx = lane & 7;
#pragma unroll
        for (int kt = 0; kt < 8; kt++) {
            int row = w * 16 + (g & 1) * 8 + idx;
            uint32_t a = cvta_s((char*)Qs + row * KSTR + kt * 32 + (g >> 1) * 16);
            ldsm_x4(qa[kt][0], qa[kt][1], qa[kt][2], qa[kt][3], a);
        }
    }

    float M0 = -1e30f, M1 = -1e30f, l0 = 0.f, l1 = 0.f;
    float o[64];
#pragma unroll
    for (int i = 0; i < 64; i++) o[i] = 0.f;

    for (int it = 0; it < niter; it++) {
        int jb = kv0 + it * 128;
        char* stg = sm + SM_ST + (it & 1) * STAGE_BYTES;
        __half* Ks = (__half*)stg;
        __half* Vs = (__half*)(stg + 128 * KSTR);

        // prefetch next stage
        if (it + 1 < niter) {
            int jn = jb + 128;
            char* nstg = sm + SM_ST + ((it + 1) & 1) * STAGE_BYTES;
#pragma unroll
            for (int p = 0; p < 16; p++) {
                int i = p * 256 + tid;
                int sel = i >= 2048;
                int ii = i & 2047;
                int r = ii >> 4, ch = ii & 15;
                int gr = min(jn + r, NN - 1);
                const char* src = sel ? (const char*)g_V : (const char*)g_K;
                uint32_t dst = cvta_s(nstg + (sel ? 128 * KSTR : 0) + r * KSTR + ch * 16);
                cp_async16(dst, src + (size_t)gr * 256 + ch * 16);
            }
            cp_commit();
            cp_wait<1>();
        } else {
            cp_wait<0>();
        }
        __syncthreads();

        float s[64];
#pragma unroll
        for (int i = 0; i < 64; i++) s[i] = 0.f;

        // S = Q @ K^T
        {
            int g = lane >> 3, idx = lane & 7;
#pragma unroll
            for (int kt = 0; kt < 8; kt++) {
#pragma unroll
                for (int nt2 = 0; nt2 < 8; nt2++) {
                    int row = nt2 * 16 + (g & 2) * 4 + idx;
                    uint32_t a = cvta_s((char*)Ks + row * KSTR + kt * 32 + (g & 1) * 16);
                    uint32_t b0, b1, b2, b3;
                    ldsm_x4(b0, b1, b2, b3, a);
                    mma_f16(s + (2 * nt2) * 4, qa[kt], b0, b1);
                    mma_f16(s + (2 * nt2 + 1) * 4, qa[kt], b2, b3);
                }
            }
        }

        // mask tail keys
        if (jb + 128 > kv1) {
#pragma unroll
            for (int nt = 0; nt < 16; nt++) {
                int j0 = jb + nt * 8 + 2 * (lane & 3);
                if (j0 >= kv1) { s[nt * 4 + 0] = -1e30f; s[nt * 4 + 2] = -1e30f; }
                if (j0 + 1 >= kv1) { s[nt * 4 + 1] = -1e30f; s[nt * 4 + 3] = -1e30f; }
            }
        }

        // online softmax (exp2 domain)
        float m0 = -1e30f, m1 = -1e30f;
#pragma unroll
        for (int nt = 0; nt < 16; nt++) {
            m0 = fmaxf(m0, fmaxf(s[nt * 4 + 0], s[nt * 4 + 1]));
            m1 = fmaxf(m1, fmaxf(s[nt * 4 + 2], s[nt * 4 + 3]));
        }
        m0 = fmaxf(m0, __shfl_xor_sync(0xffffffffu, m0, 1));
        m0 = fmaxf(m0, __shfl_xor_sync(0xffffffffu, m0, 2));
        m1 = fmaxf(m1, __shfl_xor_sync(0xffffffffu, m1, 1));
        m1 = fmaxf(m1, __shfl_xor_sync(0xffffffffu, m1, 2));
        float Mn0 = fmaxf(M0, m0), Mn1 = fmaxf(M1, m1);
        float sc0 = exp2f(M0 - Mn0), sc1 = exp2f(M1 - Mn1);
        M0 = Mn0; M1 = Mn1;
        float r0 = 0.f, r1 = 0.f;
#pragma unroll
        for (int nt = 0; nt < 16; nt++) {
            s[nt * 4 + 0] = exp2f(s[nt * 4 + 0] - M0);
            s[nt * 4 + 1] = exp2f(s[nt * 4 + 1] - M0);
            s[nt * 4 + 2] = exp2f(s[nt * 4 + 2] - M1);
            s[nt * 4 + 3] = exp2f(s[nt * 4 + 3] - M1);
            r0 += s[nt * 4 + 0] + s[nt * 4 + 1];
            r1 += s[nt * 4 + 2] + s[nt * 4 + 3];
        }
        r0 += __shfl_xor_sync(0xffffffffu, r0, 1);
        r0 += __shfl_xor_sync(0xffffffffu, r0, 2);
        r1 += __shfl_xor_sync(0xffffffffu, r1, 1);
        r1 += __shfl_xor_sync(0xffffffffu, r1, 2);
        l0 = l0 * sc0 + r0;
        l1 = l1 * sc1 + r1;
#pragma unroll
        for (int nt = 0; nt < 16; nt++) {
            o[nt * 4 + 0] *= sc0; o[nt * 4 + 1] *= sc0;
            o[nt * 4 + 2] *= sc1; o[nt * 4 + 3] *= sc1;
        }

        // O += P @ V
        {
            int g = lane >> 3, idx = lane & 7;
#pragma unroll
            for (int kt = 0; kt < 8; kt++) {
                uint32_t pa[4];
                pa[0] = packh2(s[8 * kt + 0], s[8 * kt + 1]);
                pa[1] = packh2(s[8 * kt + 2], s[8 * kt + 3]);
                pa[2] = packh2(s[8 * kt + 4], s[8 * kt + 5]);
                pa[3] = packh2(s[8 * kt + 6], s[8 * kt + 7]);
#pragma unroll
                for (int nt2 = 0; nt2 < 8; nt2++) {
                    int row = kt * 16 + (g & 1) * 8 + idx;
                    uint32_t a = cvta_s((char*)Vs + row * KSTR + nt2 * 32 + (g >> 1) * 16);
                    uint32_t b0, b1, b2, b3;
                    ldsm_x4_t(b0, b1, b2, b3, a);
                    mma_f16(o + (2 * nt2) * 4, pa, b0, b1);
                    mma_f16(o + (2 * nt2 + 1) * 4, pa, b2, b3);
                }
            }
        }
        __syncthreads();
    }

    // write partials (unnormalized o, plus m, l)
    int rr0 = w * 16 + (lane >> 2);
    int rr1 = rr0 + 8;
    size_t ubase = (size_t)unit * 128;
    if ((lane & 3) == 0) {
        g_pm[ubase + rr0] = M0;
        g_pl[ubase + rr0] = l0;
        g_pm[ubase + rr1] = M1;
        g_pl[ubase + rr1] = l1;
    }
#pragma unroll
    for (int nt = 0; nt < 16; nt++) {
        int c = nt * 8 + 2 * (lane & 3);
        *(float2*)&g_po[(ubase + rr0) * 128 + c] = make_float2(o[nt * 4 + 0], o[nt * 4 + 1]);
        *(float2*)&g_po[(ubase + rr1) * 128 + c] = make_float2(o[nt * 4 + 2], o[nt * 4 + 3]);
    }
}

// ------------- merge splits + column mean-sum -------------
__global__ void __launch_bounds__(128) merge_kernel() {
    int c = threadIdx.x;
    int rstart = blockIdx.x * 16;
    float acc = 0.f;
    for (int i = 0; i < 16; i++) {
        int r = rstart + i;
        if (r >= NN) break;
        int tile = r >> 7, row = r & 127;
        int base = tile * (NSPLIT * 128) + row;
        float M = -1e30f;
#pragma unroll
        for (int s = 0; s < NSPLIT; s++) M = fmaxf(M, g_pm[base + s * 128]);
        float L = 0.f, oc = 0.f;
#pragma unroll
        for (int s = 0; s < NSPLIT; s++) {
            float sc = exp2f(g_pm[base + s * 128] - M);
            L += g_pl[base + s * 128] * sc;
            oc += g_po[(size_t)(base + s * 128) * 128 + c] * sc;
        }
        acc += oc / L;
    }
    atomicAdd(&g_accum[c], acc);
}

// ------------- mean -> Wo -> MLP -> softmax; re-zeros g_accum -------------
__global__ void __launch_bounds__(128) final_kernel(const float* Wo, const float* bo,
                                                    const float* W1, const float* b1v,
                                                    const float* W2, const float* b2v,
                                                    const float* W3, const float* b3v,
                                                    float* out) {
    __shared__ float v0[128], v1[128], v2[64], v3[32], red[2];
    int t = threadIdx.x;
    v0[t] = g_accum[t] * (1.0f / NN);
    g_accum[t] = 0.f;   // replay invariant
    __syncthreads();
    float s = bo[t];
    for (int i = 0; i < 128; i++) s += v0[i] * Wo[i * 128 + t];
    v1[t] = s;
    __syncthreads();
    if (t < 64) {
        float s2 = b1v[t];
        for (int i = 0; i < 128; i++) s2 += v1[i] * W1[i * 64 + t];
        v2[t] = fmaxf(s2, 0.f);
    }
    __syncthreads();
    if (t < 32) {
        float s3 = b2v[t];
        for (int i = 0; i < 64; i++) s3 += v2[i] * W2[i * 32 + t];
        v3[t] = fmaxf(s3, 0.f);
    }
    __syncthreads();
    float lg = b3v[t];
    for (int i = 0; i < 32; i++) lg += v3[i] * W3[i * 128 + t];
    v1[t] = lg;
    __syncthreads();
    if (t == 0) {
        float mx = -1e30f;
        for (int i = 0; i < 128; i++) mx = fmaxf(mx, v1[i]);
        float sm = 0.f;
        for (int i = 0; i < 128; i++) sm += expf(v1[i] - mx);
        red[0] = mx; red[1] = sm;
    }
    __syncthreads();
    out[t] = expf(lg - red[0]) / red[1];
}

// ------------- launch -------------
extern "C" void kernel_launch(void* const* d_in, const int* in_sizes, int n_in,
                              void* d_out, int out_size) {
    const float* nf = (const float*)d_in[0];
    const float* gi = (const float*)d_in[1];
    const int* ei = (const int*)d_in[2];
    const float* W1_root = (const float*)d_in[3];
    const float* W1_rel = (const float*)d_in[4];
    const float* b1 = (const float*)d_in[5];
    const float* W2_root = (const float*)d_in[6];
    const float* W2_rel = (const float*)d_in[7];
    const float* b2 = (const float*)d_in[8];
    const float* WQ = (const float*)d_in[9];
    const float* bQ = (const float*)d_in[10];
    const float* WK = (const float*)d_in[11];
    const float* bK = (const float*)d_in[12];
    const float* WV = (const float*)d_in[13];
    const float* bV = (const float*)d_in[14];
    const float* WQg = (const float*)d_in[15];
    const float* bQg = (const float*)d_in[16];
    const float* WKg = (const float*)d_in[17];
    const float* bKg = (const float*)d_in[18];
    const float* WVg = (const float*)d_in[19];
    const float* bVg = (const float*)d_in[20];
    const float* Wo = (const float*)d_in[21];
    const float* bo = (const float*)d_in[22];
    const float* Wfc1 = (const float*)d_in[23];
    const float* bfc1 = (const float*)d_in[24];
    const float* Wfc2 = (const float*)d_in[25];
    const float* bfc2 = (const float*)d_in[26];
    const float* Wfc3 = (const float*)d_in[27];
    const float* bfc3 = (const float*)d_in[28];

    static int attr_set = 0;
    if (!attr_set) {
        cudaFuncSetAttribute(attn_kernel, cudaFuncAttributeMaxDynamicSharedMemorySize, SMEM_TOTAL);
        attr_set = 1;
    }

    scatter_kernel<<<20000, 256>>>(nf, ei, 0);                                   // 0 -> aggA
    conv_kernel<<<dim3(157, 2), 256>>>(nf, W1_root, W1_rel, b1, 0);              // 1 reads aggA
    scatter_kernel<<<20000, 256>>>(nf, ei, 1);                                   // 2 -> aggB
    conv_kernel<<<dim3(157, 2), 256>>>(nf, W2_root, W2_rel, b2, 1);              // 3 reads aggB, zeros aggA  <- ncu slot
    qkv_kernel<<<dim3(157, 2, 3), 256>>>(gi, WQ, bQ, WQg, bQg,
                                         WK, bK, WKg, bKg, WV, bV, WVg, bVg);    // 4 zeros aggB (m==0)
    attn_kernel<<<NQT * NSPLIT, 256, SMEM_TOTAL>>>();                            // 5
    merge_kernel<<<625, 128>>>();                                                // 6
    final_kernel<<<1, 128>>>(Wo, bo, Wfc1, bfc1, Wfc2, bfc2, Wfc3, bfc3, (float*)d_out);  // 7
}

// round 9
// speedup vs baseline: 2.3062x; 1.4500x over previous
#include <cuda_runtime.h>
#include <cuda_fp16.h>
#include <cstdint>

#define NN 10000
#define EE 160000
// log2(e)/sqrt(128) folded into Q so softmax runs in exp2 domain
#define QSCALE 0.12752532f

#define NSPLIT 8
#define CHUNK 1280
#define NQT 79          // ceil(10000/128) Q tiles

// ------------- device scratch (static, zero-initialized, no allocation) -------------
__device__ float g_aggA[NN * 128];       // scatter#1 target; zeroed by conv stage 1
__device__ float g_aggB[NN * 128];       // scatter#2 target; zeroed by qkv (m==0)
__device__ float g_h[NN * 128];          // conv0 out fp32 (scatter#2 input)
__device__ __half g_h16[NN * 128];       // conv0 out fp16 (conv1 A input)
__device__ __half g_ne16[NN * 128];      // conv1 out fp16 (qkv A input)
__device__ __half g_Q[NN * 128];
__device__ __half g_K[NN * 128];
__device__ __half g_V[NN * 128];
__device__ float g_accum[128];           // zeroed by final_kernel after read
__device__ float g_pm[NQT * NSPLIT * 128];
__device__ float g_pl[NQT * NSPLIT * 128];
__device__ float g_po[(size_t)NQT * NSPLIT * 128 * 128];

// ------------- helpers -------------
__device__ __forceinline__ uint32_t cvta_s(const void* p) {
    return (uint32_t)__cvta_generic_to_shared(p);
}
__device__ __forceinline__ void ldsm_x4(uint32_t& r0, uint32_t& r1, uint32_t& r2, uint32_t& r3, uint32_t a) {
    asm volatile("ldmatrix.sync.aligned.m8n8.x4.shared.b16 {%0,%1,%2,%3}, [%4];"
                 : "=r"(r0), "=r"(r1), "=r"(r2), "=r"(r3) : "r"(a));
}
__device__ __forceinline__ void ldsm_x4_t(uint32_t& r0, uint32_t& r1, uint32_t& r2, uint32_t& r3, uint32_t a) {
    asm volatile("ldmatrix.sync.aligned.m8n8.x4.trans.shared.b16 {%0,%1,%2,%3}, [%4];"
                 : "=r"(r0), "=r"(r1), "=r"(r2), "=r"(r3) : "r"(a));
}
__device__ __forceinline__ void mma_f16(float* c, const uint32_t* a, uint32_t b0, uint32_t b1) {
    asm volatile(
        "mma.sync.aligned.m16n8k16.row.col.f32.f16.f16.f32 "
        "{%0,%1,%2,%3},{%4,%5,%6,%7},{%8,%9},{%0,%1,%2,%3};\n"
        : "+f"(c[0]), "+f"(c[1]), "+f"(c[2]), "+f"(c[3])
        : "r"(a[0]), "r"(a[1]), "r"(a[2]), "r"(a[3]), "r"(b0), "r"(b1));
}
__device__ __forceinline__ uint32_t packh2(float lo, float hi) {
    __half2 h = __floats2half2_rn(lo, hi);
    return *reinterpret_cast<uint32_t*>(&h);
}
__device__ __forceinline__ void cp_async16(uint32_t s, const void* g) {
    asm volatile("cp.async.cg.shared.global [%0], [%1], 16;" :: "r"(s), "l"(g));
}
__device__ __forceinline__ void cp_commit() { asm volatile("cp.async.commit_group;"); }
template <int N> __device__ __forceinline__ void cp_wait() {
    asm volatile("cp.async.wait_group %0;" :: "n"(N));
}

// ------------- segment_sum(x[src], dst) -------------
__global__ void scatter_kernel(const float* __restrict__ xin, const int* __restrict__ ei, int useH) {
    const float* x = useH ? g_h : xin;
    float* agg = useH ? g_aggB : g_aggA;
    long idx = (long)blockIdx.x * 256 + threadIdx.x;
    int e = (int)(idx >> 5);
    if (e >= EE) return;
    int q = ((int)idx & 31) * 4;
    int s = ei[e];
    int d = ei[EE + e];
    float4 v = *(const float4*)(x + (size_t)s * 128 + q);
    float* dp = agg + (size_t)d * 128 + q;
    asm volatile("red.global.add.v4.f32 [%0], {%1,%2,%3,%4};"
                 :: "l"(dp), "f"(v.x), "f"(v.y), "f"(v.z), "f"(v.w) : "memory");
}

// ------------- GraphConv on tensor cores: out = [relu](X@Wr + agg@Wl + b) -------------
// grid 157, 128 thr (4 warps x 16 rows = 64 rows, full 128 cols, K=128, 2 passes).
// smem (dynamic 104448B): Xs[64x272] | As2[64x272] | Wrs[128x272] | Wls[128x272]
// stage0: A=Xin (fp32->fp16), out = relu(...) -> g_h (fp32) + g_h16
// stage1: A=g_h16 (copy), out -> g_ne16; zeros its g_aggA rows (cross-kernel safe)
#define CONV_SMEM (17408 * 2 + 34816 * 2)
__global__ void __launch_bounds__(128) convmma_kernel(const float* __restrict__ Xin,
                                                      const float* __restrict__ Wr,
                                                      const float* __restrict__ Wl,
                                                      const float* __restrict__ bias,
                                                      int stage) {
    extern __shared__ char smc[];
    char* Xs  = smc;
    char* As2 = smc + 17408;
    char* Wrs = smc + 34816;
    char* Wls = smc + 69632;
    __shared__ float bias_s[128];
    int tid = threadIdx.x, lane = tid & 31, w = tid >> 5;
    int rbase = blockIdx.x * 64;
    bias_s[tid] = bias[tid];

    const float* AGG = stage ? g_aggB : g_aggA;

    // A fill
    if (stage == 0) {
        for (int i = tid; i < 2048; i += 128) {          // 64 rows x 32 float4-groups
            int r = i >> 5, g4 = i & 31;
            int gr = rbase + r;
            float4 v = (gr < NN) ? *(const float4*)(Xin + (size_t)gr * 128 + g4 * 4)
                                 : make_float4(0.f, 0.f, 0.f, 0.f);
            uint2 u;
            u.x = packh2(v.x, v.y);
            u.y = packh2(v.z, v.w);
            *(uint2*)(Xs + r * 272 + g4 * 8) = u;
        }
    } else {
        for (int i = tid; i < 1024; i += 128) {          // 64 rows x 16 x 16B
            int r = i >> 4, ch = i & 15;
            int gr = min(rbase + r, NN - 1);             // OOB rows clamped; outputs guarded
            *(uint4*)(Xs + r * 272 + ch * 16) =
                *(const uint4*)((const char*)g_h16 + (size_t)gr * 256 + ch * 16);
        }
    }
    // agg fill (fp32 -> fp16)
    for (int i = tid; i < 2048; i += 128) {
        int r = i >> 5, g4 = i & 31;
        int gr = rbase + r;
        float4 v = (gr < NN) ? *(const float4*)(AGG + (size_t)gr * 128 + g4 * 4)
                             : make_float4(0.f, 0.f, 0.f, 0.f);
        uint2 u;
        u.x = packh2(v.x, v.y);
        u.y = packh2(v.z, v.w);
        *(uint2*)(As2 + r * 272 + g4 * 8) = u;
    }
    // W fills (fp32 -> fp16), stored row-major [k][c] like V's [key][col]
    for (int i = tid; i < 4096; i += 128) {              // 128 k-rows x 32 groups
        int k = i >> 5, g4 = i & 31;
        float4 v = *(const float4*)(Wr + (size_t)k * 128 + g4 * 4);
        uint2 u; u.x = packh2(v.x, v.y); u.y = packh2(v.z, v.w);
        *(uint2*)(Wrs + k * 272 + g4 * 8) = u;
        float4 v2 = *(const float4*)(Wl + (size_t)k * 128 + g4 * 4);
        uint2 u2; u2.x = packh2(v2.x, v2.y); u2.y = packh2(v2.z, v2.w);
        *(uint2*)(Wls + k * 272 + g4 * 8) = u2;
    }
    __syncthreads();

    int g = lane >> 3, idx = lane & 7;
    float o[64];
#pragma unroll
    for (int i = 0; i < 64; i++) o[i] = 0.f;

    // two accumulating passes: (Xs,Wrs) then (As2,Wls)
#pragma unroll
    for (int pass = 0; pass < 2; pass++) {
        char* Abuf = pass ? As2 : Xs;
        char* Wbuf = pass ? Wls : Wrs;
#pragma unroll
        for (int kt = 0; kt < 8; kt++) {
            uint32_t a[4];
            int arow = w * 16 + (g & 1) * 8 + idx;       // proven Q-preload pattern
            ldsm_x4(a[0], a[1], a[2], a[3],
                    cvta_s(Abuf + arow * 272 + kt * 32 + (g >> 1) * 16));
#pragma unroll
            for (int nt2 = 0; nt2 < 8; nt2++) {
                int row = kt * 16 + (g & 1) * 8 + idx;   // proven P@V B pattern
                uint32_t b0, b1, b2, b3;
                ldsm_x4_t(b0, b1, b2, b3,
                          cvta_s(Wbuf + row * 272 + nt2 * 32 + (g >> 1) * 16));
                mma_f16(o + (2 * nt2) * 4, a, b0, b1);
                mma_f16(o + (2 * nt2 + 1) * 4, a, b2, b3);
            }
        }
    }

    // stage1: zero our g_aggA rows (consumed by stage0; kernel boundary syncs)
    if (stage) {
        float4 z = make_float4(0.f, 0.f, 0.f, 0.f);
        for (int i = tid; i < 2048; i += 128) {
            int r = i >> 5, g4 = i & 31;
            int gr = rbase + r;
            if (gr < NN) *(float4*)(g_aggA + (size_t)gr * 128 + g4 * 4) = z;
        }
    }

    // epilogue (proven attention C-fragment writeback pattern)
    int rr0 = w * 16 + (lane >> 2), rr1 = rr0 + 8;
    int gr0 = rbase + rr0, gr1 = rbase + rr1;
#pragma unroll
    for (int nt = 0; nt < 16; nt++) {
        int c = nt * 8 + 2 * (lane & 3);
        float v00 = o[nt * 4 + 0] + bias_s[c], v01 = o[nt * 4 + 1] + bias_s[c + 1];
        float v10 = o[nt * 4 + 2] + bias_s[c], v11 = o[nt * 4 + 3] + bias_s[c + 1];
        if (stage == 0) {
            v00 = fmaxf(v00, 0.f); v01 = fmaxf(v01, 0.f);
            v10 = fmaxf(v10, 0.f); v11 = fmaxf(v11, 0.f);
            if (gr0 < NN) {
                *(float2*)(g_h + (size_t)gr0 * 128 + c) = make_float2(v00, v01);
                *(uint32_t*)((char*)g_h16 + (size_t)gr0 * 256 + c * 2) = packh2(v00, v01);
            }
            if (gr1 < NN) {
                *(float2*)(g_h + (size_t)gr1 * 128 + c) = make_float2(v10, v11);
                *(uint32_t*)((char*)g_h16 + (size_t)gr1 * 256 + c * 2) = packh2(v10, v11);
            }
        } else {
            if (gr0 < NN)
                *(uint32_t*)((char*)g_ne16 + (size_t)gr0 * 256 + c * 2) = packh2(v00, v01);
            if (gr1 < NN)
                *(uint32_t*)((char*)g_ne16 + (size_t)gr1 * 256 + c * 2) = packh2(v10, v11);
        }
    }
}

// ------------- QKV on tensor cores: out = (ne@W + b + gi@Wg + bg)*scale -> fp16 -------------
// grid (157, 3), 128 thr. smem (dynamic 52224B): Ns[64x272] | Ws[128x272]
// m==0 CTAs zero their g_aggB rows (consumed by conv stage 1).
#define QKV_SMEM (17408 + 34816)
__global__ void __launch_bounds__(128) qkvmma_kernel(const float* __restrict__ gi,
                                                     const float* __restrict__ WQ, const float* __restrict__ bQ,
                                                     const float* __restrict__ WQg, const float* __restrict__ bQg,
                                                     const float* __restrict__ WK, const float* __restrict__ bK,
                                                     const float* __restrict__ WKg, const float* __restrict__ bKg,
                                                     const float* __restrict__ WV, const float* __restrict__ bV,
                                                     const float* __restrict__ WVg, const float* __restrict__ bVg) {
    extern __shared__ char smq[];
    char* Ns = smq;
    char* Ws = smq + 17408;
    __shared__ float cb_s[128];
    int m = blockIdx.y;
    const float* W  = m == 0 ? WQ  : (m == 1 ? WK  : WV);
    const float* b  = m == 0 ? bQ  : (m == 1 ? bK  : bV);
    const float* bg = m == 0 ? bQg : (m == 1 ? bKg : bVg);
    const float* Wg = m == 0 ? WQg : (m == 1 ? WKg : WVg);
    __half* out = m == 0 ? g_Q : (m == 1 ? g_K : g_V);
    float scale = m == 0 ? QSCALE : 1.0f;
    int tid = threadIdx.x, lane = tid & 31, w = tid >> 5;
    int rbase = blockIdx.x * 64;

    // combined bias (per-column dot over 64 global dims)
    {
        float s = b[tid] + bg[tid];
        for (int i = 0; i < 64; i++) s += gi[i] * Wg[i * 128 + tid];
        cb_s[tid] = s;
    }
    // ne fill (fp16 copy)
    for (int i = tid; i < 1024; i += 128) {
        int r = i >> 4, ch = i & 15;
        int gr = min(rbase + r, NN - 1);
        *(uint4*)(Ns + r * 272 + ch * 16) =
            *(const uint4*)((const char*)g_ne16 + (size_t)gr * 256 + ch * 16);
    }
    // W fill (fp32 -> fp16)
    for (int i = tid; i < 4096; i += 128) {
        int k = i >> 5, g4 = i & 31;
        float4 v = *(const float4*)(W + (size_t)k * 128 + g4 * 4);
        uint2 u; u.x = packh2(v.x, v.y); u.y = packh2(v.z, v.w);
        *(uint2*)(Ws + k * 272 + g4 * 8) = u;
    }
    __syncthreads();

    int g = lane >> 3, idx = lane & 7;
    float o[64];
#pragma unroll
    for (int i = 0; i < 64; i++) o[i] = 0.f;

#pragma unroll
    for (int kt = 0; kt < 8; kt++) {
        uint32_t a[4];
        int arow = w * 16 + (g & 1) * 8 + idx;
        ldsm_x4(a[0], a[1], a[2], a[3],
                cvta_s(Ns + arow * 272 + kt * 32 + (g >> 1) * 16));
#pragma unroll
        for (int nt2 = 0; nt2 < 8; nt2++) {
            int row = kt * 16 + (g & 1) * 8 + idx;
            uint32_t b0, b1, b2, b3;
            ldsm_x4_t(b0, b1, b2, b3,
                      cvta_s(Ws + row * 272 + nt2 * 32 + (g >> 1) * 16));
            mma_f16(o + (2 * nt2) * 4, a, b0, b1);
            mma_f16(o + (2 * nt2 + 1) * 4, a, b2, b3);
        }
    }

    // m==0: zero our g_aggB rows (replay invariant; race-free after conv stage 1)
    if (m == 0) {
        float4 z = make_float4(0.f, 0.f, 0.f, 0.f);
        for (int i = tid; i < 2048; i += 128) {
            int r = i >> 5, g4 = i & 31;
            int gr = rbase + r;
            if (gr < NN) *(float4*)(g_aggB + (size_t)gr * 128 + g4 * 4) = z;
        }
    }

    int rr0 = w * 16 + (lane >> 2), rr1 = rr0 + 8;
    int gr0 = rbase + rr0, gr1 = rbase + rr1;
#pragma unroll
    for (int nt = 0; nt < 16; nt++) {
        int c = nt * 8 + 2 * (lane & 3);
        float v00 = (o[nt * 4 + 0] + cb_s[c]) * scale, v01 = (o[nt * 4 + 1] + cb_s[c + 1]) * scale;
        float v10 = (o[nt * 4 + 2] + cb_s[c]) * scale, v11 = (o[nt * 4 + 3] + cb_s[c + 1]) * scale;
        if (gr0 < NN) *(uint32_t*)((char*)out + (size_t)gr0 * 256 + c * 2) = packh2(v00, v01);
        if (gr1 < NN) *(uint32_t*)((char*)out + (size_t)gr1 * 256 + c * 2) = packh2(v10, v11);
    }
}

// ------------- split-KV flash attention (proven version: Br=128, Bc=128) -------------
#define KSTR 272
#define SM_Q 0
#define SM_ST (128 * KSTR)
#define STAGE_BYTES (2 * 128 * KSTR)
#define SMEM_TOTAL (128 * KSTR + 2 * STAGE_BYTES)

__global__ void __launch_bounds__(256, 1) attn_kernel() {
    extern __shared__ char sm[];
    __half* Qs = (__half*)(sm + SM_Q);
    int tid = threadIdx.x, lane = tid & 31, w = tid >> 5;
    int unit = blockIdx.x;
    int qtile = unit / NSPLIT, split = unit - qtile * NSPLIT;
    int rbase = qtile * 128;
    int kv0 = split * CHUNK;
    int kv1 = min(kv0 + CHUNK, NN);
    int niter = (kv1 - kv0 + 127) >> 7;

    for (int i = tid; i < 128 * 16; i += 256) {
        int r = i >> 4, ch = i & 15;
        int gr = min(rbase + r, NN - 1);
        *(uint4*)((char*)Qs + r * KSTR + ch * 16) =
            *(const uint4*)((const char*)g_Q + (size_t)gr * 256 + ch * 16);
    }

    {
        int jb = kv0;
#pragma unroll
        for (int p = 0; p < 16; p++) {
            int i = p * 256 + tid;
            int sel = i >= 2048;
            int ii = i & 2047;
            int r = ii >> 4, ch = ii & 15;
            int gr = min(jb + r, NN - 1);
            const char* src = sel ? (const char*)g_V : (const char*)g_K;
            uint32_t dst = cvta_s(sm + SM_ST + (sel ? 128 * KSTR : 0) + r * KSTR + ch * 16);
            cp_async16(dst, src + (size_t)gr * 256 + ch * 16);
        }
        cp_commit();
    }
    __syncthreads();

    uint32_t qa[8][4];
    {
        int g = lane >> 3, idx = lane & 7;
#pragma unroll
        for (int kt = 0; kt < 8; kt++) {
            int row = w * 16 + (g & 1) * 8 + idx;
            uint32_t a = cvta_s((char*)Qs + row * KSTR + kt * 32 + (g >> 1) * 16);
            ldsm_x4(qa[kt][0], qa[kt][1], qa[kt][2], qa[kt][3], a);
        }
    }

    float M0 = -1e30f, M1 = -1e30f, l0 = 0.f, l1 = 0.f;
    float o[64];
#pragma unroll
    for (int i = 0; i < 64; i++) o[i] = 0.f;

    for (int it = 0; it < niter; it++) {
        int jb = kv0 + it * 128;
        char* stg = sm + SM_ST + (it & 1) * STAGE_BYTES;
        __half* Ks = (__half*)stg;
        __half* Vs = (__half*)(stg + 128 * KSTR);

        if (it + 1 < niter) {
            int jn = jb + 128;
            char* nstg = sm + SM_ST + ((it + 1) & 1) * STAGE_BYTES;
#pragma unroll
            for (int p = 0; p < 16; p++) {
                int i = p * 256 + tid;
                int sel = i >= 2048;
                int ii = i & 2047;
                int r = ii >> 4, ch = ii & 15;
                int gr = min(jn + r, NN - 1);
                const char* src = sel ? (const char*)g_V : (const char*)g_K;
                uint32_t dst = cvta_s(nstg + (sel ? 128 * KSTR : 0) + r * KSTR + ch * 16);
                cp_async16(dst, src + (size_t)gr * 256 + ch * 16);
            }
            cp_commit();
            cp_wait<1>();
        } else {
            cp_wait<0>();
        }
        __syncthreads();

        float s[64];
#pragma unroll
        for (int i = 0; i < 64; i++) s[i] = 0.f;

        {
            int g = lane >> 3, idx = lane & 7;
#pragma unroll
            for (int kt = 0; kt < 8; kt++) {
#pragma unroll
                for (int nt2 = 0; nt2 < 8; nt2++) {
                    int row = nt2 * 16 + (g & 2) * 4 + idx;
                    uint32_t a = cvta_s((char*)Ks + row * KSTR + kt * 32 + (g & 1) * 16);
                    uint32_t b0, b1, b2, b3;
                    ldsm_x4(b0, b1, b2, b3, a);
                    mma_f16(s + (2 * nt2) * 4, qa[kt], b0, b1);
                    mma_f16(s + (2 * nt2 + 1) * 4, qa[kt], b2, b3);
                }
            }
        }

        if (jb + 128 > kv1) {
#pragma unroll
            for (int nt = 0; nt < 16; nt++) {
                int j0 = jb + nt * 8 + 2 * (lane & 3);
                if (j0 >= kv1) { s[nt * 4 + 0] = -1e30f; s[nt * 4 + 2] = -1e30f; }
                if (j0 + 1 >= kv1) { s[nt * 4 + 1] = -1e30f; s[nt * 4 + 3] = -1e30f; }
            }
        }

        float m0 = -1e30f, m1 = -1e30f;
#pragma unroll
        for (int nt = 0; nt < 16; nt++) {
            m0 = fmaxf(m0, fmaxf(s[nt * 4 + 0], s[nt * 4 + 1]));
            m1 = fmaxf(m1, fmaxf(s[nt * 4 + 2], s[nt * 4 + 3]));
        }
        m0 = fmaxf(m0, __shfl_xor_sync(0xffffffffu, m0, 1));
        m0 = fmaxf(m0, __shfl_xor_sync(0xffffffffu, m0, 2));
        m1 = fmaxf(m1, __shfl_xor_sync(0xffffffffu, m1, 1));
        m1 = fmaxf(m1, __shfl_xor_sync(0xffffffffu, m1, 2));
        float Mn0 = fmaxf(M0, m0), Mn1 = fmaxf(M1, m1);
        float sc0 = exp2f(M0 - Mn0), sc1 = exp2f(M1 - Mn1);
        M0 = Mn0; M1 = Mn1;
        float r0 = 0.f, r1 = 0.f;
#pragma unroll
        for (int nt = 0; nt < 16; nt++) {
            s[nt * 4 + 0] = exp2f(s[nt * 4 + 0] - M0);
            s[nt * 4 + 1] = exp2f(s[nt * 4 + 1] - M0);
            s[nt * 4 + 2] = exp2f(s[nt * 4 + 2] - M1);
            s[nt * 4 + 3] = exp2f(s[nt * 4 + 3] - M1);
            r0 += s[nt * 4 + 0] + s[nt * 4 + 1];
            r1 += s[nt * 4 + 2] + s[nt * 4 + 3];
        }
        r0 += __shfl_xor_sync(0xffffffffu, r0, 1);
        r0 += __shfl_xor_sync(0xffffffffu, r0, 2);
        r1 += __shfl_xor_sync(0xffffffffu, r1, 1);
        r1 += __shfl_xor_sync(0xffffffffu, r1, 2);
        l0 = l0 * sc0 + r0;
        l1 = l1 * sc1 + r1;
#pragma unroll
        for (int nt = 0; nt < 16; nt++) {
            o[nt * 4 + 0] *= sc0; o[nt * 4 + 1] *= sc0;
            o[nt * 4 + 2] *= sc1; o[nt * 4 + 3] *= sc1;
        }

        {
            int g = lane >> 3, idx = lane & 7;
#pragma unroll
            for (int kt = 0; kt < 8; kt++) {
                uint32_t pa[4];
                pa[0] = packh2(s[8 * kt + 0], s[8 * kt + 1]);
                pa[1] = packh2(s[8 * kt + 2], s[8 * kt + 3]);
                pa[2] = packh2(s[8 * kt + 4], s[8 * kt + 5]);
                pa[3] = packh2(s[8 * kt + 6], s[8 * kt + 7]);
#pragma unroll
                for (int nt2 = 0; nt2 < 8; nt2++) {
                    int row = kt * 16 + (g & 1) * 8 + idx;
                    uint32_t a = cvta_s((char*)Vs + row * KSTR + nt2 * 32 + (g >> 1) * 16);
                    uint32_t b0, b1, b2, b3;
                    ldsm_x4_t(b0, b1, b2, b3, a);
                    mma_f16(o + (2 * nt2) * 4, pa, b0, b1);
                    mma_f16(o + (2 * nt2 + 1) * 4, pa, b2, b3);
                }
            }
        }
        __syncthreads();
    }

    int rr0 = w * 16 + (lane >> 2);
    int rr1 = rr0 + 8;
    size_t ubase = (size_t)unit * 128;
    if ((lane & 3) == 0) {
        g_pm[ubase + rr0] = M0;
        g_pl[ubase + rr0] = l0;
        g_pm[ubase + rr1] = M1;
        g_pl[ubase + rr1] = l1;
    }
#pragma unroll
    for (int nt = 0; nt < 16; nt++) {
        int c = nt * 8 + 2 * (lane & 3);
        *(float2*)&g_po[(ubase + rr0) * 128 + c] = make_float2(o[nt * 4 + 0], o[nt * 4 + 1]);
        *(float2*)&g_po[(ubase + rr1) * 128 + c] = make_float2(o[nt * 4 + 2], o[nt * 4 + 3]);
    }
}

// ------------- merge splits + column mean-sum -------------
__global__ void __launch_bounds__(128) merge_kernel() {
    int c = threadIdx.x;
    int rstart = blockIdx.x * 16;
    float acc = 0.f;
    for (int i = 0; i < 16; i++) {
        int r = rstart + i;
        if (r >= NN) break;
        int tile = r >> 7, row = r & 127;
        int base = tile * (NSPLIT * 128) + row;
        float M = -1e30f;
#pragma unroll
        for (int s = 0; s < NSPLIT; s++) M = fmaxf(M, g_pm[base + s * 128]);
        float L = 0.f, oc = 0.f;
#pragma unroll
        for (int s = 0; s < NSPLIT; s++) {
            float sc = exp2f(g_pm[base + s * 128] - M);
            L += g_pl[base + s * 128] * sc;
            oc += g_po[(size_t)(base + s * 128) * 128 + c] * sc;
        }
        acc += oc / L;
    }
    atomicAdd(&g_accum[c], acc);
}

// ------------- mean -> Wo -> MLP -> softmax; re-zeros g_accum -------------
__global__ void __launch_bounds__(128) final_kernel(const float* Wo, const float* bo,
                                                    const float* W1, const float* b1v,
                                                    const float* W2, const float* b2v,
                                                    const float* W3, const float* b3v,
                                                    float* out) {
    __shared__ float v0[128], v1[128], v2[64], v3[32], red[2];
    int t = threadIdx.x;
    v0[t] = g_accum[t] * (1.0f / NN);
    g_accum[t] = 0.f;   // replay invariant
    __syncthreads();
    float s = bo[t];
    for (int i = 0; i < 128; i++) s += v0[i] * Wo[i * 128 + t];
    v1[t] = s;
    __syncthreads();
    if (t < 64) {
        float s2 = b1v[t];
        for (int i = 0; i < 128; i++) s2 += v1[i] * W1[i * 64 + t];
        v2[t] = fmaxf(s2, 0.f);
    }
    __syncthreads();
    if (t < 32) {
        float s3 = b2v[t];
        for (int i = 0; i < 64; i++) s3 += v2[i] * W2[i * 32 + t];
        v3[t] = fmaxf(s3, 0.f);
    }
    __syncthreads();
    float lg = b3v[t];
    for (int i = 0; i < 32; i++) lg += v3[i] * W3[i * 128 + t];
    v1[t] = lg;
    __syncthreads();
    if (t == 0) {
        float mx = -1e30f;
        for (int i = 0; i < 128; i++) mx = fmaxf(mx, v1[i]);
        float sm = 0.f;
        for (int i = 0; i < 128; i++) sm += expf(v1[i] - mx);
        red[0] = mx; red[1] = sm;
    }
    __syncthreads();
    out[t] = expf(lg - red[0]) / red[1];
}

// ------------- launch -------------
extern "C" void kernel_launch(void* const* d_in, const int* in_sizes, int n_in,
                              void* d_out, int out_size) {
    const float* nf = (const float*)d_in[0];
    const float* gi = (const float*)d_in[1];
    const int* ei = (const int*)d_in[2];
    const float* W1_root = (const float*)d_in[3];
    const float* W1_rel = (const float*)d_in[4];
    const float* b1 = (const float*)d_in[5];
    const float* W2_root = (const float*)d_in[6];
    const float* W2_rel = (const float*)d_in[7];
    const float* b2 = (const float*)d_in[8];
    const float* WQ = (const float*)d_in[9];
    const float* bQ = (const float*)d_in[10];
    const float* WK = (const float*)d_in[11];
    const float* bK = (const float*)d_in[12];
    const float* WV = (const float*)d_in[13];
    const float* bV = (const float*)d_in[14];
    const float* WQg = (const float*)d_in[15];
    const float* bQg = (const float*)d_in[16];
    const float* WKg = (const float*)d_in[17];
    const float* bKg = (const float*)d_in[18];
    const float* WVg = (const float*)d_in[19];
    const float* bVg = (const float*)d_in[20];
    const float* Wo = (const float*)d_in[21];
    const float* bo = (const float*)d_in[22];
    const float* Wfc1 = (const float*)d_in[23];
    const float* bfc1 = (const float*)d_in[24];
    const float* Wfc2 = (const float*)d_in[25];
    const float* bfc2 = (const float*)d_in[26];
    const float* Wfc3 = (const float*)d_in[27];
    const float* bfc3 = (const float*)d_in[28];

    static int attr_set = 0;
    if (!attr_set) {
        cudaFuncSetAttribute(attn_kernel, cudaFuncAttributeMaxDynamicSharedMemorySize, SMEM_TOTAL);
        cudaFuncSetAttribute(convmma_kernel, cudaFuncAttributeMaxDynamicSharedMemorySize, CONV_SMEM);
        cudaFuncSetAttribute(qkvmma_kernel, cudaFuncAttributeMaxDynamicSharedMemorySize, QKV_SMEM);
        attr_set = 1;
    }

    scatter_kernel<<<20000, 256>>>(nf, ei, 0);                                   // 0 -> aggA
    convmma_kernel<<<157, 128, CONV_SMEM>>>(nf, W1_root, W1_rel, b1, 0);         // 1 reads aggA
    scatter_kernel<<<20000, 256>>>(nf, ei, 1);                                   // 2 -> aggB
    convmma_kernel<<<157, 128, CONV_SMEM>>>(nf, W2_root, W2_rel, b2, 1);         // 3 reads aggB, zeros aggA  <- ncu slot
    qkvmma_kernel<<<dim3(157, 3), 128, QKV_SMEM>>>(gi, WQ, bQ, WQg, bQg,
                                                   WK, bK, WKg, bKg,
                                                   WV, bV, WVg, bVg);            // 4 zeros aggB (m==0)
    attn_kernel<<<NQT * NSPLIT, 256, SMEM_TOTAL>>>();                            // 5
    merge_kernel<<<625, 128>>>();                                                // 6
    final_kernel<<<1, 128>>>(Wo, bo, Wfc1, bfc1, Wfc2, bfc2, Wfc3, bfc3, (float*)d_out);  // 7
}